// round 2
// baseline (speedup 1.0000x reference)
#include <cuda_runtime.h>

// Fused transformer block: LN1 -> 2-head causal attn -> +res -> LN2 -> FFN -> +res
// B=2048, T=128, DM=32, H=2, DK=16. One CTA per batch element, one thread per token.

namespace {
constexpr int Bsz = 2048;
constexpr int T   = 128;
constexpr int DM  = 32;
constexpr int FF  = 128;
constexpr int KV_STRIDE = 36;   // 32 + 4 pad: keeps 16B alignment, kills STS.128 full conflicts

// shared memory layout (floats)
constexpr int OFF_W1 = 0;                      // 4096 floats (aliases Wq|Wk|Wv = 3072 in phase A)
constexpr int OFF_W2 = 4096;                   // 4096
constexpr int OFF_WO = 8192;                   // 1024
constexpr int OFF_K  = 9216;                   // 128*36 = 4608
constexpr int OFF_V  = OFF_K + T * KV_STRIDE;  // 13824
constexpr int OFF_Bb = OFF_V + T * KV_STRIDE;  // 18432 : bo[32] b1[128] b2[32] g1[32] be1[32] g2[32] be2[32]
constexpr int SMEM_FLOATS = OFF_Bb + 320;      // 18752
constexpr int SMEM_BYTES  = SMEM_FLOATS * 4;   // 75008 B -> 3 CTAs/SM
}

__global__ void __launch_bounds__(128, 3) block_kernel(
    const float* __restrict__ gx,
    const float* __restrict__ gWq, const float* __restrict__ gWk, const float* __restrict__ gWv,
    const float* __restrict__ gWo, const float* __restrict__ gbo,
    const float* __restrict__ gW1, const float* __restrict__ gb1,
    const float* __restrict__ gW2, const float* __restrict__ gb2,
    const float* __restrict__ gg1, const float* __restrict__ gbe1,
    const float* __restrict__ gg2, const float* __restrict__ gbe2,
    float* __restrict__ gout)
{
    extern __shared__ float sm[];
    float* sQKV = sm + OFF_W1;     // phase A: Wq(1024) Wk(1024) Wv(1024)
    float* sW1  = sm + OFF_W1;     // phase B: W1 (4096)
    float* sW2  = sm + OFF_W2;
    float* sWo  = sm + OFF_WO;
    float* sK   = sm + OFF_K;
    float* sV   = sm + OFF_V;
    float* sbo  = sm + OFF_Bb;
    float* sb1  = sm + OFF_Bb + 32;
    float* sb2  = sm + OFF_Bb + 160;
    float* sg1  = sm + OFF_Bb + 192;
    float* sbe1 = sm + OFF_Bb + 224;
    float* sg2  = sm + OFF_Bb + 256;
    float* sbe2 = sm + OFF_Bb + 288;

    const int tid = threadIdx.x;
    const int b   = blockIdx.x;

    // ---- phase A cooperative loads: Wq|Wk|Wv, Wo, W2, biases ----
    {
        float4*       dq = (float4*)sQKV;
        const float4* s;
        s = (const float4*)gWq; for (int i = tid; i < 256;  i += 128) dq[i]       = s[i];
        s = (const float4*)gWk; for (int i = tid; i < 256;  i += 128) dq[256 + i] = s[i];
        s = (const float4*)gWv; for (int i = tid; i < 256;  i += 128) dq[512 + i] = s[i];
        float4* d2 = (float4*)sW2; s = (const float4*)gW2; for (int i = tid; i < 1024; i += 128) d2[i] = s[i];
        float4* d3 = (float4*)sWo; s = (const float4*)gWo; for (int i = tid; i < 256;  i += 128) d3[i] = s[i];
        if (tid < 32) {
            sbo[tid]  = gbo[tid];  sb2[tid]  = gb2[tid];
            sg1[tid]  = gg1[tid];  sbe1[tid] = gbe1[tid];
            sg2[tid]  = gg2[tid];  sbe2[tid] = gbe2[tid];
        }
        sb1[tid] = gb1[tid];
    }
    __syncthreads();

    // ---- load x row, LN1 ----
    float xr[DM];
    {
        const float4* xrow = (const float4*)(gx + ((long)b * T + tid) * DM);
        #pragma unroll
        for (int i = 0; i < 8; i++) {
            float4 v = xrow[i];
            xr[4*i] = v.x; xr[4*i+1] = v.y; xr[4*i+2] = v.z; xr[4*i+3] = v.w;
        }
        float mu = 0.f;
        #pragma unroll
        for (int d = 0; d < DM; d++) mu += xr[d];
        mu *= (1.f / DM);
        float var = 0.f;
        #pragma unroll
        for (int d = 0; d < DM; d++) { float c = xr[d] - mu; var = fmaf(c, c, var); }
        var *= (1.f / DM);
        float r = rsqrtf(var + 1e-5f);
        #pragma unroll
        for (int d = 0; d < DM; d++) xr[d] = (xr[d] - mu) * r * sg1[d] + sbe1[d];
    }

    // ---- q, k, v projections (broadcast LDS.128 + 4 FMA inner) ----
    float q[DM];
    #pragma unroll
    for (int g = 0; g < 8; g++) {   // h = g/4, j0 = (g%4)*4; q index = 4*g + c
        const float* wp = sQKV + (g / 4) * 512 + (g % 4) * 4;
        float a0 = 0.f, a1 = 0.f, a2 = 0.f, a3 = 0.f;
        #pragma unroll
        for (int d = 0; d < DM; d++) {
            float4 w = *(const float4*)(wp + d * 16);
            a0 = fmaf(xr[d], w.x, a0); a1 = fmaf(xr[d], w.y, a1);
            a2 = fmaf(xr[d], w.z, a2); a3 = fmaf(xr[d], w.w, a3);
        }
        q[4*g] = a0; q[4*g+1] = a1; q[4*g+2] = a2; q[4*g+3] = a3;
    }
    #pragma unroll
    for (int g = 0; g < 8; g++) {   // k row -> smem
        const float* wp = sQKV + 1024 + (g / 4) * 512 + (g % 4) * 4;
        float a0 = 0.f, a1 = 0.f, a2 = 0.f, a3 = 0.f;
        #pragma unroll
        for (int d = 0; d < DM; d++) {
            float4 w = *(const float4*)(wp + d * 16);
            a0 = fmaf(xr[d], w.x, a0); a1 = fmaf(xr[d], w.y, a1);
            a2 = fmaf(xr[d], w.z, a2); a3 = fmaf(xr[d], w.w, a3);
        }
        *(float4*)(sK + tid * KV_STRIDE + 4 * g) = make_float4(a0, a1, a2, a3);
    }
    #pragma unroll
    for (int g = 0; g < 8; g++) {   // v row -> smem
        const float* wp = sQKV + 2048 + (g / 4) * 512 + (g % 4) * 4;
        float a0 = 0.f, a1 = 0.f, a2 = 0.f, a3 = 0.f;
        #pragma unroll
        for (int d = 0; d < DM; d++) {
            float4 w = *(const float4*)(wp + d * 16);
            a0 = fmaf(xr[d], w.x, a0); a1 = fmaf(xr[d], w.y, a1);
            a2 = fmaf(xr[d], w.z, a2); a3 = fmaf(xr[d], w.w, a3);
        }
        *(float4*)(sV + tid * KV_STRIDE + 4 * g) = make_float4(a0, a1, a2, a3);
    }
    __syncthreads();   // k,v visible; everyone done with sQKV

    // overwrite sQKV region with W1 (overlaps with attention compute; fenced before FFN)
    {
        const float4* s = (const float4*)gW1;
        float4*       d = (float4*)sW1;
        for (int i = tid; i < 1024; i += 128) d[i] = s[i];
    }

    // ---- causal attention, streaming softmax (no max-shift: |score| <= ~32, provably safe) ----
    float acc[DM];
    #pragma unroll
    for (int j = 0; j < DM; j++) acc[j] = 0.f;
    float l0 = 0.f, l1 = 0.f;

    for (int s = 0; s <= tid; s++) {
        const float* kp = sK + s * KV_STRIDE;     // broadcast across active lanes
        float4 k0 = *(const float4*)(kp +  0);
        float4 k1 = *(const float4*)(kp +  4);
        float4 k2 = *(const float4*)(kp +  8);
        float4 k3 = *(const float4*)(kp + 12);
        float a = q[0]*k0.x, bb = q[1]*k0.y, c = q[2]*k0.z, e = q[3]*k0.w;
        a = fmaf(q[4],  k1.x, a); bb = fmaf(q[5],  k1.y, bb); c = fmaf(q[6],  k1.z, c); e = fmaf(q[7],  k1.w, e);
        a = fmaf(q[8],  k2.x, a); bb = fmaf(q[9],  k2.y, bb); c = fmaf(q[10], k2.z, c); e = fmaf(q[11], k2.w, e);
        a = fmaf(q[12], k3.x, a); bb = fmaf(q[13], k3.y, bb); c = fmaf(q[14], k3.z, c); e = fmaf(q[15], k3.w, e);
        float d0 = (a + bb) + (c + e);

        float4 k4 = *(const float4*)(kp + 16);
        float4 k5 = *(const float4*)(kp + 20);
        float4 k6 = *(const float4*)(kp + 24);
        float4 k7 = *(const float4*)(kp + 28);
        a = q[16]*k4.x; bb = q[17]*k4.y; c = q[18]*k4.z; e = q[19]*k4.w;
        a = fmaf(q[20], k5.x, a); bb = fmaf(q[21], k5.y, bb); c = fmaf(q[22], k5.z, c); e = fmaf(q[23], k5.w, e);
        a = fmaf(q[24], k6.x, a); bb = fmaf(q[25], k6.y, bb); c = fmaf(q[26], k6.z, c); e = fmaf(q[27], k6.w, e);
        a = fmaf(q[28], k7.x, a); bb = fmaf(q[29], k7.y, bb); c = fmaf(q[30], k7.z, c); e = fmaf(q[31], k7.w, e);
        float d1 = (a + bb) + (c + e);

        float p0 = __expf(d0), p1 = __expf(d1);
        l0 += p0; l1 += p1;

        const float* vp = sV + s * KV_STRIDE;
        #pragma unroll
        for (int g = 0; g < 4; g++) {
            float4 vv = *(const float4*)(vp + 4 * g);
            acc[4*g]   = fmaf(p0, vv.x, acc[4*g]);
            acc[4*g+1] = fmaf(p0, vv.y, acc[4*g+1]);
            acc[4*g+2] = fmaf(p0, vv.z, acc[4*g+2]);
            acc[4*g+3] = fmaf(p0, vv.w, acc[4*g+3]);
        }
        #pragma unroll
        for (int g = 4; g < 8; g++) {
            float4 vv = *(const float4*)(vp + 4 * g);
            acc[4*g]   = fmaf(p1, vv.x, acc[4*g]);
            acc[4*g+1] = fmaf(p1, vv.y, acc[4*g+1]);
            acc[4*g+2] = fmaf(p1, vv.z, acc[4*g+2]);
            acc[4*g+3] = fmaf(p1, vv.w, acc[4*g+3]);
        }
    }
    {
        float inv0 = 1.f / l0, inv1 = 1.f / l1;
        #pragma unroll
        for (int j = 0; j < 16; j++) acc[j] *= inv0;
        #pragma unroll
        for (int j = 16; j < 32; j++) acc[j] *= inv1;
    }

    // ---- attn @ Wo + bo + residual (residual is post-LN1 x) ----
    float x1[DM];
    #pragma unroll
    for (int dg = 0; dg < 8; dg++) {
        float a0 = 0.f, a1 = 0.f, a2 = 0.f, a3 = 0.f;
        #pragma unroll
        for (int e = 0; e < DM; e++) {
            float4 w = *(const float4*)(sWo + e * 32 + dg * 4);
            a0 = fmaf(acc[e], w.x, a0); a1 = fmaf(acc[e], w.y, a1);
            a2 = fmaf(acc[e], w.z, a2); a3 = fmaf(acc[e], w.w, a3);
        }
        x1[4*dg]   = xr[4*dg]   + a0 + sbo[4*dg];
        x1[4*dg+1] = xr[4*dg+1] + a1 + sbo[4*dg+1];
        x1[4*dg+2] = xr[4*dg+2] + a2 + sbo[4*dg+2];
        x1[4*dg+3] = xr[4*dg+3] + a3 + sbo[4*dg+3];
    }

    // ---- LN2 (FFN residual wraps the POST-LN2 x, per reference) ----
    float x2[DM];
    {
        float mu = 0.f;
        #pragma unroll
        for (int d = 0; d < DM; d++) mu += x1[d];
        mu *= (1.f / DM);
        float var = 0.f;
        #pragma unroll
        for (int d = 0; d < DM; d++) { float cc = x1[d] - mu; var = fmaf(cc, cc, var); }
        var *= (1.f / DM);
        float r = rsqrtf(var + 1e-5f);
        #pragma unroll
        for (int d = 0; d < DM; d++) x2[d] = (x1[d] - mu) * r * sg2[d] + sbe2[d];
    }

    __syncthreads();   // W1 fully staged by all threads

    // ---- FFN: out = x2 + relu(x2@W1 + b1) @ W2 + b2, hidden fused (no storage) ----
    float res[DM];
    #pragma unroll
    for (int d = 0; d < DM; d++) res[d] = x2[d] + sb2[d];

    for (int j0 = 0; j0 < FF; j0 += 4) {
        float h0 = sb1[j0], h1 = sb1[j0+1], h2 = sb1[j0+2], h3 = sb1[j0+3];
        #pragma unroll
        for (int d = 0; d < DM; d++) {
            float4 w = *(const float4*)(sW1 + d * FF + j0);
            h0 = fmaf(x2[d], w.x, h0); h1 = fmaf(x2[d], w.y, h1);
            h2 = fmaf(x2[d], w.z, h2); h3 = fmaf(x2[d], w.w, h3);
        }
        h0 = fmaxf(h0, 0.f); h1 = fmaxf(h1, 0.f); h2 = fmaxf(h2, 0.f); h3 = fmaxf(h3, 0.f);
        #pragma unroll
        for (int dg = 0; dg < 8; dg++) {
            float4 w0 = *(const float4*)(sW2 + (j0 + 0) * 32 + dg * 4);
            float4 w1 = *(const float4*)(sW2 + (j0 + 1) * 32 + dg * 4);
            float4 w2 = *(const float4*)(sW2 + (j0 + 2) * 32 + dg * 4);
            float4 w3 = *(const float4*)(sW2 + (j0 + 3) * 32 + dg * 4);
            float r0 = res[4*dg], r1 = res[4*dg+1], r2 = res[4*dg+2], r3 = res[4*dg+3];
            r0 = fmaf(h0, w0.x, r0); r1 = fmaf(h0, w0.y, r1); r2 = fmaf(h0, w0.z, r2); r3 = fmaf(h0, w0.w, r3);
            r0 = fmaf(h1, w1.x, r0); r1 = fmaf(h1, w1.y, r1); r2 = fmaf(h1, w1.z, r2); r3 = fmaf(h1, w1.w, r3);
            r0 = fmaf(h2, w2.x, r0); r1 = fmaf(h2, w2.y, r1); r2 = fmaf(h2, w2.z, r2); r3 = fmaf(h2, w2.w, r3);
            r0 = fmaf(h3, w3.x, r0); r1 = fmaf(h3, w3.y, r1); r2 = fmaf(h3, w3.z, r2); r3 = fmaf(h3, w3.w, r3);
            res[4*dg] = r0; res[4*dg+1] = r1; res[4*dg+2] = r2; res[4*dg+3] = r3;
        }
    }

    // ---- store ----
    float4* op = (float4*)(gout + ((long)b * T + tid) * DM);
    #pragma unroll
    for (int i = 0; i < 8; i++)
        op[i] = make_float4(res[4*i], res[4*i+1], res[4*i+2], res[4*i+3]);
}

extern "C" void kernel_launch(void* const* d_in, const int* in_sizes, int n_in,
                              void* d_out, int out_size)
{
    const float* x   = (const float*)d_in[0];
    const float* Wq  = (const float*)d_in[1];
    const float* Wk  = (const float*)d_in[2];
    const float* Wv  = (const float*)d_in[3];
    const float* Wo  = (const float*)d_in[4];
    const float* bo  = (const float*)d_in[5];
    const float* W1  = (const float*)d_in[6];
    const float* b1  = (const float*)d_in[7];
    const float* W2  = (const float*)d_in[8];
    const float* b2  = (const float*)d_in[9];
    const float* g1  = (const float*)d_in[10];
    const float* be1 = (const float*)d_in[11];
    const float* g2  = (const float*)d_in[12];
    const float* be2 = (const float*)d_in[13];
    float* out = (float*)d_out;

    cudaFuncSetAttribute(block_kernel, cudaFuncAttributeMaxDynamicSharedMemorySize, SMEM_BYTES);
    block_kernel<<<Bsz, 128, SMEM_BYTES>>>(x, Wq, Wk, Wv, Wo, bo, W1, b1, W2, b2,
                                           g1, be1, g2, be2, out);
}